// round 2
// baseline (speedup 1.0000x reference)
#include <cuda_runtime.h>

#define VV   400000
#define DD   200
#define CC   45
#define BSN  4096      // B*S
#define SS   128       // S (sequence length; window padding is per-sequence)
#define KN   12
#define KC   10
#define KT   22
#define F5   1000      // 5*D

// ---- kernel 2 tiling ----
#define TT    32       // tokens per block  (4096/32 = 128 blocks; 32 divides 128)
#define CPAD  48       // c padded to multiple of 4
#define WS    1002     // padded W row stride (floats) -> 501 float2, reduces LDS conflicts
#define NT2   384      // threads (12 warps): 96 tiles (12 cgrp x 8 tgrp) x 4 k-splits

// scratch: feat [4096, 200]
__device__ float g_feat[BSN * DD];

// ============================================================
// Kernel 1: masked gather + mean  -> g_feat
// one block per token, 128 threads, float2 over D
// ============================================================
__global__ __launch_bounds__(128) void feat_kernel(
    const int* __restrict__ ng_ids, const int* __restrict__ ng_mask,
    const int* __restrict__ cx_ids, const int* __restrict__ cx_mask,
    const float* __restrict__ embed)
{
    const int tok = blockIdx.x;
    const int tid = threadIdx.x;

    __shared__ int raw_ids[KT], raw_msk[KT];
    __shared__ int s_ids[KT];
    __shared__ int s_n;
    __shared__ float s_inv;

    if (tid < KN) {
        raw_ids[tid] = ng_ids[tok * KN + tid];
        raw_msk[tid] = ng_mask[tok * KN + tid];
    } else if (tid < KT) {
        const int j = tid - KN;
        raw_ids[tid] = cx_ids[tok * KC + j];
        raw_msk[tid] = cx_mask[tok * KC + j];
    }
    __syncthreads();

    if (tid == 0) {
        int n = 0;
        #pragma unroll
        for (int i = 0; i < KT; i++)
            if (raw_msk[i]) s_ids[n++] = raw_ids[i];
        s_n = n;
        s_inv = 1.0f / (float)(n > 0 ? n : 1);
    }
    __syncthreads();

    const int n = s_n;
    const float inv = s_inv;

    if (tid < DD / 2) {
        float sx = 0.f, sy = 0.f;
        #pragma unroll 4
        for (int i = 0; i < n; i++) {
            const long long row = (long long)s_ids[i] * DD;
            const float2 v = *(const float2*)&embed[row + tid * 2];
            sx += v.x; sy += v.y;
        }
        *(float2*)&g_feat[(long long)tok * DD + tid * 2] = make_float2(sx * inv, sy * inv);
    }
}

// ============================================================
// Kernel 2: windowed matmul  out[t,c] = b[c] + dot(window(t), W[c,:])
// window(t) is 1000 contiguous floats of the halo-padded feat tile.
// Halo is padded PER SEQUENCE (128 tokens): rows outside the tile's
// batch are zero, matching jnp.pad on axis=1.
// W in shared (padded rows), packed f32x2 FMA, 4c x 4t register tile,
// 4-way k split reduced via warp shuffle.
// ============================================================
__device__ __forceinline__ void ffma2(unsigned long long& d,
                                      unsigned long long a,
                                      unsigned long long b)
{
    asm volatile("fma.rn.f32x2 %0, %1, %2, %0;" : "+l"(d) : "l"(a), "l"(b));
}

extern __shared__ float smem2[];

__global__ __launch_bounds__(NT2) void gemm_kernel(
    const float* __restrict__ W, const float* __restrict__ bias,
    float* __restrict__ out)
{
    float* sW = smem2;                 // CPAD * WS floats
    float* sX = smem2 + CPAD * WS;     // (TT+4) * DD floats (halo rows)

    const int tid = threadIdx.x;
    const int t0  = blockIdx.x * TT;
    const int b0  = t0 / SS;           // batch index of this tile (TT divides SS)

    // ---- load W into padded shared rows (float2 granularity) ----
    {
        unsigned long long*       sW2 = (unsigned long long*)sW;
        const unsigned long long* W2  = (const unsigned long long*)W;
        const int total = (CC * F5) / 2;                // 22500 float2
        for (int i = tid; i < total; i += NT2) {
            const int c = i / (F5 / 2);
            const int f = i % (F5 / 2);
            sW2[c * (WS / 2) + f] = W2[i];
        }
        // zero pad rows 45..47 (read by dead lanes of the c-tile)
        const int padtot = (CPAD - CC) * (WS / 2);
        for (int i = tid; i < padtot; i += NT2)
            sW2[CC * (WS / 2) + i] = 0ull;
        // zero the per-row pad tail (deterministic)
        for (int i = tid; i < CC; i += NT2)
            sW2[i * (WS / 2) + (F5 / 2)] = 0ull;
    }

    // ---- load X tile with +-2 halo rows (float4), zero outside this batch ----
    {
        float4*       sX4   = (float4*)sX;
        const float4* feat4 = (const float4*)g_feat;
        const int total = ((TT + 4) * DD) / 4;          // 1800 float4
        for (int i = tid; i < total; i += NT2) {
            const int row = i / (DD / 4);
            const int col = i % (DD / 4);
            const int g = t0 + row - 2;
            // valid only within the same sequence (per-batch zero padding);
            // arithmetic shift maps g<0 to -1, g>=BSN to b0+1 -> both invalid
            const bool ok = ((g >> 7) == b0);
            sX4[i] = ok ? feat4[(long long)g * (DD / 4) + col]
                        : make_float4(0.f, 0.f, 0.f, 0.f);
        }
    }
    __syncthreads();

    // thread decomposition: 96 tiles x 4 k-splits
    const int ks    = tid & 3;
    const int tile  = tid >> 2;       // 0..95
    const int cg    = tile % 12;      // c group (4 c's)
    const int tg    = tile / 12;      // t group (4 t's), 0..7
    const int cbase = cg * 4;
    const int tbase = tg * 4;

    unsigned long long acc[4][4];
    #pragma unroll
    for (int i = 0; i < 4; i++)
        #pragma unroll
        for (int j = 0; j < 4; j++) acc[i][j] = 0ull;

    const unsigned long long* sW2 = (const unsigned long long*)sW;
    const unsigned long long* sX2 = (const unsigned long long*)sX;

    const int k0 = ks * 125;          // float2 index within the 500-float2 window
    #pragma unroll 1
    for (int kk = k0; kk < k0 + 125; kk++) {
        unsigned long long w[4], x[4];
        #pragma unroll
        for (int j = 0; j < 4; j++) w[j] = sW2[(cbase + j) * (WS / 2) + kk];
        #pragma unroll
        for (int i = 0; i < 4; i++) x[i] = sX2[(tbase + i) * (DD / 2) + kk];
        #pragma unroll
        for (int i = 0; i < 4; i++)
            #pragma unroll
            for (int j = 0; j < 4; j++)
                ffma2(acc[i][j], x[i], w[j]);
    }

    // ---- reduce packed halves + across 4 k-splits (adjacent lanes) ----
    #pragma unroll
    for (int i = 0; i < 4; i++) {
        #pragma unroll
        for (int j = 0; j < 4; j++) {
            const unsigned long long a = acc[i][j];
            float v = __uint_as_float((unsigned)(a & 0xffffffffull)) +
                      __uint_as_float((unsigned)(a >> 32));
            v += __shfl_xor_sync(0xffffffffu, v, 1);
            v += __shfl_xor_sync(0xffffffffu, v, 2);
            if (ks == 0) {
                const int c = cbase + j;
                if (c < CC)
                    out[(long long)(t0 + tbase + i) * CC + c] = v + bias[c];
            }
        }
    }
}

// ============================================================
extern "C" void kernel_launch(void* const* d_in, const int* in_sizes, int n_in,
                              void* d_out, int out_size)
{
    const int*   ng_ids  = (const int*)d_in[0];
    const int*   ng_mask = (const int*)d_in[1];
    const int*   cx_ids  = (const int*)d_in[2];
    const int*   cx_mask = (const int*)d_in[3];
    const float* embed   = (const float*)d_in[4];
    const float* W       = (const float*)d_in[5];
    const float* bias    = (const float*)d_in[6];
    float*       out     = (float*)d_out;

    feat_kernel<<<BSN, 128>>>(ng_ids, ng_mask, cx_ids, cx_mask, embed);

    const size_t smem = (size_t)(CPAD * WS + (TT + 4) * DD) * sizeof(float); // 221,184 B
    cudaFuncSetAttribute(gemm_kernel, cudaFuncAttributeMaxDynamicSharedMemorySize, (int)smem);
    gemm_kernel<<<BSN / TT, NT2, smem>>>(W, bias, out);
}